// round 1
// baseline (speedup 1.0000x reference)
#include <cuda_runtime.h>
#include <math.h>

#define B_ 512
#define C_ 64
#define H_ 128
#define P_ 16
#define G_ 2
#define EPS_ 1e-5f

// ---------------- device scratch (static, allocation-free) ----------------
__device__ float  g_ec[C_ * H_];      // layernormed emb_column
__device__ float  g_hp[P_ * H_];      // ep @ W1^T + lin_b + ep   (batch-independent part of hat)
__device__ float  g_W2t[H_ * H_];     // W2^T: g_W2t[k*H + h] = lin_w[h*2H + H + k]
__device__ float4 g_pc[P_];           // per-prompt: {|w|, max(-w,0), gn_w, gn_b}
__device__ float  g_gc[2 * 4];        // per-group: {A1=sum|w|, A2=sum v, B1=sum u^2, B2=sum v^2}

// ---------------- K1: tiny setup (1 block, 256 threads) ----------------
__global__ void setup_kernel(const float* __restrict__ emb_column,
                             const float* __restrict__ emb_prompt,
                             const float* __restrict__ lin_w,
                             const float* __restrict__ lin_b,
                             const float* __restrict__ ln_col_w,
                             const float* __restrict__ ln_col_b,
                             const float* __restrict__ ln_pr_w,
                             const float* __restrict__ ln_pr_b,
                             const float* __restrict__ expand_weight,
                             const float* __restrict__ gn_w,
                             const float* __restrict__ gn_b)
{
    __shared__ float s_ep[P_][H_];
    const int tid  = threadIdx.x;
    const int warp = tid >> 5;
    const int lane = tid & 31;

    // LayerNorm rows: 0..63 -> ec, 64..79 -> ep
    for (int r = warp; r < C_ + P_; r += 8) {
        const float* src; const float* wv; const float* bv;
        if (r < C_) { src = emb_column + r * H_;        wv = ln_col_w; bv = ln_col_b; }
        else        { src = emb_prompt + (r - C_) * H_; wv = ln_pr_w;  bv = ln_pr_b;  }
        float v[4];
        float s = 0.f, ss = 0.f;
        #pragma unroll
        for (int i = 0; i < 4; i++) {
            v[i] = src[lane + 32 * i];
            s += v[i]; ss += v[i] * v[i];
        }
        #pragma unroll
        for (int o = 16; o > 0; o >>= 1) {
            s  += __shfl_xor_sync(0xffffffffu, s,  o);
            ss += __shfl_xor_sync(0xffffffffu, ss, o);
        }
        const float mu  = s * (1.f / H_);
        const float var = ss * (1.f / H_) - mu * mu;
        const float inv = rsqrtf(var + EPS_);
        #pragma unroll
        for (int i = 0; i < 4; i++) {
            const int h = lane + 32 * i;
            const float o = (v[i] - mu) * inv * wv[h] + bv[h];
            if (r < C_) g_ec[r * H_ + h] = o;
            else        s_ep[r - C_][h]  = o;
        }
    }
    __syncthreads();

    // hp[p,h] = sum_k ep[p,k]*W1[h,k] + lin_b[h] + ep[p,h]
    {
        const int h  = tid & 127;
        const int pb = tid >> 7;
        float acc[8];
        #pragma unroll
        for (int j = 0; j < 8; j++) {
            const int p = pb + 2 * j;
            acc[j] = lin_b[h] + s_ep[p][h];
        }
        for (int k = 0; k < H_; k++) {
            const float wk = lin_w[h * (2 * H_) + k];
            #pragma unroll
            for (int j = 0; j < 8; j++)
                acc[j] += s_ep[pb + 2 * j][k] * wk;
        }
        #pragma unroll
        for (int j = 0; j < 8; j++)
            g_hp[(pb + 2 * j) * H_ + h] = acc[j];
    }

    // W2 transpose for coalesced GEMM reads
    for (int i = tid; i < H_ * H_; i += 256) {
        const int k = i >> 7, h = i & 127;
        g_W2t[i] = lin_w[h * (2 * H_) + H_ + k];
    }

    // per-prompt coefficients
    if (tid < P_) {
        const float w  = expand_weight[tid];
        const float aw = fabsf(w);
        const float v  = fmaxf(-w, 0.f);
        g_pc[tid] = make_float4(aw, v, gn_w[tid], gn_b[tid]);
    }
    __syncthreads();
    if (tid == 0) {
        for (int g = 0; g < 2; g++) {
            float A1 = 0.f, A2 = 0.f, B1 = 0.f, B2 = 0.f;
            for (int p = g * 8; p < g * 8 + 8; p++) {
                const float4 pc = g_pc[p];
                const float aw = pc.x, v = pc.y;
                const float u  = aw - v;   // max(w,0)
                A1 += aw; A2 += v; B1 += u * u; B2 += v * v;
            }
            g_gc[g * 4 + 0] = A1; g_gc[g * 4 + 1] = A2;
            g_gc[g * 4 + 2] = B1; g_gc[g * 4 + 3] = B2;
        }
    }
}

// ---------------- K2: fused per-batch kernel (512 blocks, 256 threads) ----------------
// smem layout (floats): ec[64][129] | x[64][129] | xp[16*128] | hat[16*128] | m[16*64] | red[32] | grp[4]
#define SM_EC   0
#define SM_X    (64 * 129)
#define SM_XP   (SM_X + 64 * 129)
#define SM_HAT  (SM_XP + 16 * 128)
#define SM_M    (SM_HAT + 16 * 128)
#define SM_RED  (SM_M + 16 * 64)
#define SM_GRP  (SM_RED + 32)
#define SM_FLOATS (SM_GRP + 4)

extern __shared__ float sm[];

__global__ void __launch_bounds__(256, 2)
trompt_main_kernel(const float* __restrict__ x,
                   const float* __restrict__ x_prompt,
                   float* __restrict__ out)
{
    float* s_ec  = sm + SM_EC;
    float* s_x   = sm + SM_X;
    float* s_xp  = sm + SM_XP;
    float* s_hat = sm + SM_HAT;
    float* s_m   = sm + SM_M;
    float* s_red = sm + SM_RED;
    float* s_grp = sm + SM_GRP;

    const int tid = threadIdx.x;
    const int b   = blockIdx.x;

    // cooperative loads
    const float* xb = x + (size_t)b * (C_ * H_);
    for (int i = tid; i < C_ * H_; i += 256) {
        const int r = i >> 7, cc = i & 127;
        s_ec[r * 129 + cc] = g_ec[i];
        s_x [r * 129 + cc] = xb[i];
    }
    const float* xpb = x_prompt + (size_t)b * (P_ * H_);
    for (int i = tid; i < P_ * H_; i += 256) s_xp[i] = xpb[i];
    __syncthreads();

    // ---- phase 1: hat[p,h] = hp[p,h] + xp[p,h] + sum_k xp[p,k] * W2t[k,h]
    {
        const int h  = tid & 127;
        const int pb = tid >> 7;
        float acc[8];
        #pragma unroll
        for (int j = 0; j < 8; j++) {
            const int p = pb + 2 * j;
            acc[j] = g_hp[p * H_ + h] + s_xp[p * H_ + h];
        }
        for (int k = 0; k < H_; k++) {
            const float wv = g_W2t[k * H_ + h];
            #pragma unroll
            for (int j = 0; j < 8; j++)
                acc[j] += s_xp[(pb + 2 * j) * H_ + k] * wv;
        }
        #pragma unroll
        for (int j = 0; j < 8; j++)
            s_hat[(pb + 2 * j) * H_ + h] = acc[j];
    }
    __syncthreads();

    // ---- phase 2: logits m[p,c] = sum_h hat[p,h] * ec[c,h]
    {
        const int c  = tid & 63;
        const int pq = tid >> 6;
        float acc[4] = {0.f, 0.f, 0.f, 0.f};
        for (int h = 0; h < H_; h++) {
            const float e = s_ec[c * 129 + h];
            #pragma unroll
            for (int j = 0; j < 4; j++)
                acc[j] += s_hat[(pq + 4 * j) * H_ + h] * e;
        }
        #pragma unroll
        for (int j = 0; j < 4; j++)
            s_m[(pq + 4 * j) * 64 + c] = acc[j];
    }
    __syncthreads();

    const int warp = tid >> 5, lane = tid & 31;

    // ---- phase 3a: per-batch stats over x (S1=sum relu, Sx=sum x, Sr2=sum relu^2, Sx2=sum x^2)
    float s1 = 0.f, sx = 0.f, sr2 = 0.f, sx2 = 0.f;
    for (int i = tid; i < C_ * H_; i += 256) {
        const float v = s_x[(i >> 7) * 129 + (i & 127)];
        const float r = fmaxf(v, 0.f);
        s1 += r; sx += v; sr2 += r * r; sx2 += v * v;
    }
    #pragma unroll
    for (int o = 16; o > 0; o >>= 1) {
        s1  += __shfl_xor_sync(0xffffffffu, s1,  o);
        sx  += __shfl_xor_sync(0xffffffffu, sx,  o);
        sr2 += __shfl_xor_sync(0xffffffffu, sr2, o);
        sx2 += __shfl_xor_sync(0xffffffffu, sx2, o);
    }
    if (lane == 0) {
        s_red[warp * 4 + 0] = s1;  s_red[warp * 4 + 1] = sx;
        s_red[warp * 4 + 2] = sr2; s_red[warp * 4 + 3] = sx2;
    }

    // ---- phase 3b: softmax over c (each warp owns 2 prompt rows; no cross-warp hazard)
    #pragma unroll
    for (int rr = 0; rr < 2; rr++) {
        const int p = warp + rr * 8;
        float v0 = s_m[p * 64 + lane];
        float v1 = s_m[p * 64 + 32 + lane];
        float mx = fmaxf(v0, v1);
        #pragma unroll
        for (int o = 16; o > 0; o >>= 1)
            mx = fmaxf(mx, __shfl_xor_sync(0xffffffffu, mx, o));
        const float e0 = __expf(v0 - mx);
        const float e1 = __expf(v1 - mx);
        float s = e0 + e1;
        #pragma unroll
        for (int o = 16; o > 0; o >>= 1)
            s += __shfl_xor_sync(0xffffffffu, s, o);
        const float inv = 1.f / s;
        s_m[p * 64 + lane]      = e0 * inv;
        s_m[p * 64 + 32 + lane] = e1 * inv;
    }
    __syncthreads();

    // ---- phase 3c: fold stats into per-group (mu, rsqrt(var+eps))
    if (tid == 0) {
        float S1 = 0.f, Sx = 0.f, Sr2 = 0.f, Sx2 = 0.f;
        #pragma unroll
        for (int w = 0; w < 8; w++) {
            S1 += s_red[w * 4 + 0]; Sx  += s_red[w * 4 + 1];
            Sr2 += s_red[w * 4 + 2]; Sx2 += s_red[w * 4 + 3];
        }
        const float invN = 1.f / 65536.f;  // (P/G)*C*H
        #pragma unroll
        for (int g = 0; g < 2; g++) {
            const float A1 = g_gc[g * 4 + 0], A2 = g_gc[g * 4 + 1];
            const float B1 = g_gc[g * 4 + 2], B2 = g_gc[g * 4 + 3];
            const float mu = (A1 * S1 - A2 * Sx) * invN;
            const float E2 = (B1 * Sr2 + B2 * (Sx2 - Sr2)) * invN;
            const float var = E2 - mu * mu;
            s_grp[g * 2 + 0] = mu;
            s_grp[g * 2 + 1] = rsqrtf(var + EPS_);
        }
    }
    __syncthreads();

    // ---- phase 4: out[p,h] = c1*sum_c m*relu(x) + c2*sum_c m*x + c3
    {
        const int h  = tid & 127;
        const int pb = tid >> 7;
        float c1[8], c2[8], c3[8], Rm[8], Xm[8];
        #pragma unroll
        for (int j = 0; j < 8; j++) {
            const int p = pb + 2 * j;
            const float4 pc = g_pc[p];
            const int g = p >> 3;
            const float mu = s_grp[g * 2 + 0];
            const float rs = s_grp[g * 2 + 1];
            const float gr = pc.z * rs;          // gn_w * rsqrt
            c1[j] = gr * pc.x;                   // * |w_p|
            c2[j] = 1.f - gr * pc.y;             // 1 - gn_w*rs*max(-w,0)
            c3[j] = pc.w - gr * mu;              // gn_b - gn_w*rs*mu
            Rm[j] = 0.f; Xm[j] = 0.f;
        }
        for (int c = 0; c < C_; c++) {
            const float xv = s_x[c * 129 + h];
            const float rv = fmaxf(xv, 0.f);
            #pragma unroll
            for (int j = 0; j < 8; j++) {
                const float mm = s_m[(pb + 2 * j) * 64 + c];
                Rm[j] += mm * rv;
                Xm[j] += mm * xv;
            }
        }
        float* ob = out + (size_t)b * (P_ * H_);
        #pragma unroll
        for (int j = 0; j < 8; j++) {
            const int p = pb + 2 * j;
            ob[p * H_ + h] = c1[j] * Rm[j] + c2[j] * Xm[j] + c3[j];
        }
    }
}

// ---------------- launch ----------------
extern "C" void kernel_launch(void* const* d_in, const int* in_sizes, int n_in,
                              void* d_out, int out_size)
{
    const float* x            = (const float*)d_in[0];
    const float* x_prompt     = (const float*)d_in[1];
    const float* emb_column   = (const float*)d_in[2];
    const float* emb_prompt   = (const float*)d_in[3];
    const float* lin_w        = (const float*)d_in[4];
    const float* lin_b        = (const float*)d_in[5];
    const float* ln_col_w     = (const float*)d_in[6];
    const float* ln_col_b     = (const float*)d_in[7];
    const float* ln_pr_w      = (const float*)d_in[8];
    const float* ln_pr_b      = (const float*)d_in[9];
    const float* expand_w     = (const float*)d_in[10];
    const float* gn_w         = (const float*)d_in[11];
    const float* gn_b         = (const float*)d_in[12];
    float* out = (float*)d_out;

    const int smemBytes = SM_FLOATS * (int)sizeof(float);   // 86,672 B
    cudaFuncSetAttribute(trompt_main_kernel,
                         cudaFuncAttributeMaxDynamicSharedMemorySize, smemBytes);

    setup_kernel<<<1, 256>>>(emb_column, emb_prompt, lin_w, lin_b,
                             ln_col_w, ln_col_b, ln_pr_w, ln_pr_b,
                             expand_w, gn_w, gn_b);
    trompt_main_kernel<<<B_, 256, smemBytes>>>(x, x_prompt, out);
}

// round 2
// speedup vs baseline: 1.4462x; 1.4462x over previous
#include <cuda_runtime.h>
#include <math.h>

#define B_ 512
#define C_ 64
#define H_ 128
#define P_ 16
#define G_ 2
#define EPS_ 1e-5f

// ---------------- device scratch (static, allocation-free) ----------------
__device__ float  g_ec[C_ * H_];      // layernormed emb_column
__device__ float  g_hp[P_ * H_];      // ep @ W1^T + lin_b + ep   (batch-independent part of hat)
__device__ float  g_W2t[H_ * H_];     // W2^T: g_W2t[k*H + h] = lin_w[h*2H + H + k]
__device__ float4 g_pc[P_];           // per-prompt: {|w|, max(-w,0), gn_w, gn_b}
__device__ float  g_gc[2 * 4];        // per-group: {A1, A2, B1, B2}

// ---------------- K1: parallel setup (6 blocks, 256 threads) ----------------
__global__ void setup_kernel(const float* __restrict__ emb_column,
                             const float* __restrict__ emb_prompt,
                             const float* __restrict__ lin_w,
                             const float* __restrict__ lin_b,
                             const float* __restrict__ ln_col_w,
                             const float* __restrict__ ln_col_b,
                             const float* __restrict__ ln_pr_w,
                             const float* __restrict__ ln_pr_b,
                             const float* __restrict__ expand_weight,
                             const float* __restrict__ gn_w,
                             const float* __restrict__ gn_b)
{
    __shared__ float s_ep[P_][H_];       // block 0
    __shared__ float s_t[H_ * 33];       // block 0: W1 k-tile [128h][32k+pad]
    __shared__ float s_tt[32 * 129];     // blocks 2..5: transpose tile [32h][128k+pad]

    const int tid  = threadIdx.x;
    const int warp = tid >> 5;
    const int lane = tid & 31;
    const int bid  = blockIdx.x;

    if (bid == 1) {
        // ---- layernorm emb_column -> g_ec
        for (int r = warp; r < C_; r += 8) {
            const float* src = emb_column + r * H_;
            float v[4]; float s = 0.f, ss = 0.f;
            #pragma unroll
            for (int i = 0; i < 4; i++) { v[i] = src[lane + 32 * i]; s += v[i]; ss += v[i] * v[i]; }
            #pragma unroll
            for (int o = 16; o > 0; o >>= 1) {
                s  += __shfl_xor_sync(0xffffffffu, s,  o);
                ss += __shfl_xor_sync(0xffffffffu, ss, o);
            }
            const float mu  = s * (1.f / H_);
            const float inv = rsqrtf(ss * (1.f / H_) - mu * mu + EPS_);
            #pragma unroll
            for (int i = 0; i < 4; i++) {
                const int h = lane + 32 * i;
                g_ec[r * H_ + h] = (v[i] - mu) * inv * ln_col_w[h] + ln_col_b[h];
            }
        }
        return;
    }

    if (bid >= 2) {
        // ---- coalesced W2 transpose: h-chunk of 32 rows
        const int h0 = (bid - 2) * 32;
        #pragma unroll
        for (int i = 0; i < 16; i++) {
            const int idx = tid + i * 256;           // 0..4095
            const int hh = idx >> 7, kk = idx & 127;
            s_tt[hh * 129 + kk] = lin_w[(h0 + hh) * (2 * H_) + H_ + kk];
        }
        __syncthreads();
        #pragma unroll
        for (int i = 0; i < 16; i++) {
            const int idx = tid + i * 256;
            const int k = idx >> 5, hl = idx & 31;
            g_W2t[k * H_ + h0 + hl] = s_tt[hl * 129 + k];
        }
        return;
    }

    // ---- block 0: layernorm emb_prompt, hp GEMM, coefficients
    for (int r = warp; r < P_; r += 8) {
        const float* src = emb_prompt + r * H_;
        float v[4]; float s = 0.f, ss = 0.f;
        #pragma unroll
        for (int i = 0; i < 4; i++) { v[i] = src[lane + 32 * i]; s += v[i]; ss += v[i] * v[i]; }
        #pragma unroll
        for (int o = 16; o > 0; o >>= 1) {
            s  += __shfl_xor_sync(0xffffffffu, s,  o);
            ss += __shfl_xor_sync(0xffffffffu, ss, o);
        }
        const float mu  = s * (1.f / H_);
        const float inv = rsqrtf(ss * (1.f / H_) - mu * mu + EPS_);
        #pragma unroll
        for (int i = 0; i < 4; i++) {
            const int h = lane + 32 * i;
            s_ep[r][h] = (v[i] - mu) * inv * ln_pr_w[h] + ln_pr_b[h];
        }
    }
    __syncthreads();

    // hp[p,h] = sum_k ep[p,k]*W1[h,k] + lin_b[h] + ep[p,h], k-tiled via smem (coalesced)
    {
        const int h  = tid & 127;
        const int pb = tid >> 7;
        float acc[8];
        #pragma unroll
        for (int j = 0; j < 8; j++) acc[j] = lin_b[h] + s_ep[pb + 2 * j][h];

        for (int kt = 0; kt < H_; kt += 32) {
            #pragma unroll
            for (int i = 0; i < 16; i++) {
                const int idx = tid + i * 256;       // 0..4095 = 128h x 32k
                const int hh = idx >> 5, jj = idx & 31;
                s_t[hh * 33 + jj] = lin_w[hh * (2 * H_) + kt + jj];
            }
            __syncthreads();
            #pragma unroll
            for (int j2 = 0; j2 < 32; j2++) {
                const float wk = s_t[h * 33 + j2];
                #pragma unroll
                for (int j = 0; j < 8; j++)
                    acc[j] += s_ep[pb + 2 * j][kt + j2] * wk;
            }
            __syncthreads();
        }
        #pragma unroll
        for (int j = 0; j < 8; j++)
            g_hp[(pb + 2 * j) * H_ + h] = acc[j];
    }

    if (tid == 0) {
        #pragma unroll
        for (int p = 0; p < P_; p++) {
            const float w  = expand_weight[p];
            g_pc[p] = make_float4(fabsf(w), fmaxf(-w, 0.f), gn_w[p], gn_b[p]);
        }
        for (int g = 0; g < 2; g++) {
            float A1 = 0.f, A2 = 0.f, B1 = 0.f, B2 = 0.f;
            for (int p = g * 8; p < g * 8 + 8; p++) {
                const float w  = expand_weight[p];
                const float aw = fabsf(w);
                const float v  = fmaxf(-w, 0.f);
                const float u  = aw - v;
                A1 += aw; A2 += v; B1 += u * u; B2 += v * v;
            }
            g_gc[g * 4 + 0] = A1; g_gc[g * 4 + 1] = A2;
            g_gc[g * 4 + 2] = B1; g_gc[g * 4 + 3] = B2;
        }
    }
}

// ---------------- K2: fused per-batch kernel (512 blocks, 512 threads) ----------------
// smem (floats): ec[64][132] | x[64][128] | xp/hat[16][128] | m[16][64] | red[64] | grp[8]
#define SM_EC   0
#define SM_X    (64 * 132)
#define SM_XP   (SM_X + 64 * 128)
#define SM_M    (SM_XP + 16 * 128)
#define SM_RED  (SM_M + 16 * 64)
#define SM_GRP  (SM_RED + 64)
#define SM_FLOATS (SM_GRP + 8)

extern __shared__ float sm[];

__global__ void __launch_bounds__(512, 2)
trompt_main_kernel(const float* __restrict__ x,
                   const float* __restrict__ x_prompt,
                   float* __restrict__ out)
{
    float* s_ec  = sm + SM_EC;
    float* s_x   = sm + SM_X;
    float* s_xp  = sm + SM_XP;   // reused as hat after phase 1
    float* s_m   = sm + SM_M;
    float* s_red = sm + SM_RED;
    float* s_grp = sm + SM_GRP;

    const int tid = threadIdx.x;
    const int b   = blockIdx.x;

    // ---- cooperative vectorized loads
    {
        const float4* xb4 = (const float4*)(x + (size_t)b * (C_ * H_));
        #pragma unroll
        for (int i = 0; i < 4; i++)
            *(float4*)(s_x + (tid + i * 512) * 4) = xb4[tid + i * 512];

        const float4* ec4 = (const float4*)g_ec;
        #pragma unroll
        for (int i = 0; i < 4; i++) {
            const int e = tid + i * 512;
            const float4 v = ec4[e];
            const int idx = e * 4;
            *(float4*)(s_ec + (idx >> 7) * 132 + (idx & 127)) = v;
        }

        const float4* xp4 = (const float4*)(x_prompt + (size_t)b * (P_ * H_));
        *(float4*)(s_xp + tid * 4) = xp4[tid];
    }
    __syncthreads();

    // ---- phase 1: hat[p,h] = hp[p,h] + xp[p,h] + sum_k xp[p,k]*W2t[k,h]
    const int h  = tid & 127;
    const int pb = tid >> 7;   // 0..3
    {
        float acc[4];
        #pragma unroll
        for (int j = 0; j < 4; j++) {
            const int p = pb + 4 * j;
            acc[j] = g_hp[p * H_ + h] + s_xp[p * H_ + h];
        }
        for (int k = 0; k < H_; k += 4) {
            float w0 = g_W2t[(k + 0) * H_ + h];
            float w1 = g_W2t[(k + 1) * H_ + h];
            float w2 = g_W2t[(k + 2) * H_ + h];
            float w3 = g_W2t[(k + 3) * H_ + h];
            #pragma unroll
            for (int j = 0; j < 4; j++) {
                const float4 xp = *(const float4*)(s_xp + (pb + 4 * j) * H_ + k);
                acc[j] += xp.x * w0 + xp.y * w1 + xp.z * w2 + xp.w * w3;
            }
        }
        __syncthreads();   // all reads of s_xp done before overwrite
        #pragma unroll
        for (int j = 0; j < 4; j++)
            s_xp[(pb + 4 * j) * H_ + h] = acc[j];
    }
    __syncthreads();

    // ---- phase 2: m[p,c] = sum_h hat[p,h] * ec[c,h]   (vectorized LDS.128)
    {
        const int c  = tid & 63;
        const int pq = tid >> 6;   // 0..7
        float a0 = 0.f, a1 = 0.f;
        for (int hh = 0; hh < H_; hh += 4) {
            const float4 e  = *(const float4*)(s_ec + c * 132 + hh);
            const float4 t0 = *(const float4*)(s_xp + pq * H_ + hh);
            const float4 t1 = *(const float4*)(s_xp + (pq + 8) * H_ + hh);
            a0 += e.x * t0.x + e.y * t0.y + e.z * t0.z + e.w * t0.w;
            a1 += e.x * t1.x + e.y * t1.y + e.z * t1.z + e.w * t1.w;
        }
        s_m[pq * 64 + c]       = a0;
        s_m[(pq + 8) * 64 + c] = a1;
    }
    __syncthreads();

    const int warp = tid >> 5, lane = tid & 31;

    // ---- phase 3a: batch stats over x
    {
        float s1 = 0.f, sx = 0.f, sr2 = 0.f, sx2 = 0.f;
        #pragma unroll
        for (int i = 0; i < 4; i++) {
            const float4 v = *(const float4*)(s_x + (tid + i * 512) * 4);
            float vv[4] = {v.x, v.y, v.z, v.w};
            #pragma unroll
            for (int q = 0; q < 4; q++) {
                const float r = fmaxf(vv[q], 0.f);
                s1 += r; sx += vv[q]; sr2 += r * r; sx2 += vv[q] * vv[q];
            }
        }
        #pragma unroll
        for (int o = 16; o > 0; o >>= 1) {
            s1  += __shfl_xor_sync(0xffffffffu, s1,  o);
            sx  += __shfl_xor_sync(0xffffffffu, sx,  o);
            sr2 += __shfl_xor_sync(0xffffffffu, sr2, o);
            sx2 += __shfl_xor_sync(0xffffffffu, sx2, o);
        }
        if (lane == 0) {
            s_red[warp * 4 + 0] = s1;  s_red[warp * 4 + 1] = sx;
            s_red[warp * 4 + 2] = sr2; s_red[warp * 4 + 3] = sx2;
        }
    }

    // ---- phase 3b: softmax rows (warp w owns prompt row w; 16 warps)
    {
        const int p = warp;
        float v0 = s_m[p * 64 + lane];
        float v1 = s_m[p * 64 + 32 + lane];
        float mx = fmaxf(v0, v1);
        #pragma unroll
        for (int o = 16; o > 0; o >>= 1)
            mx = fmaxf(mx, __shfl_xor_sync(0xffffffffu, mx, o));
        const float e0 = __expf(v0 - mx);
        const float e1 = __expf(v1 - mx);
        float s = e0 + e1;
        #pragma unroll
        for (int o = 16; o > 0; o >>= 1)
            s += __shfl_xor_sync(0xffffffffu, s, o);
        const float inv = 1.f / s;
        s_m[p * 64 + lane]      = e0 * inv;
        s_m[p * 64 + 32 + lane] = e1 * inv;
    }
    __syncthreads();

    // ---- phase 3c: fold into per-group (mu, rsqrt)
    if (tid == 0) {
        float S1 = 0.f, Sx = 0.f, Sr2 = 0.f, Sx2 = 0.f;
        #pragma unroll
        for (int w = 0; w < 16; w++) {
            S1 += s_red[w * 4 + 0]; Sx  += s_red[w * 4 + 1];
            Sr2 += s_red[w * 4 + 2]; Sx2 += s_red[w * 4 + 3];
        }
        const float invN = 1.f / 65536.f;
        #pragma unroll
        for (int g = 0; g < 2; g++) {
            const float A1 = g_gc[g * 4 + 0], A2 = g_gc[g * 4 + 1];
            const float B1 = g_gc[g * 4 + 2], B2 = g_gc[g * 4 + 3];
            const float mu = (A1 * S1 - A2 * Sx) * invN;
            const float E2 = (B1 * Sr2 + B2 * (Sx2 - Sr2)) * invN;
            s_grp[g * 2 + 0] = mu;
            s_grp[g * 2 + 1] = rsqrtf(E2 - mu * mu + EPS_);
        }
    }
    __syncthreads();

    // ---- phase 4: out[p,h] = c1*sum_c m*relu(x) + c2*sum_c m*x + c3
    {
        float c1[4], c2[4], c3[4], Rm[4] = {0,0,0,0}, Xm[4] = {0,0,0,0};
        #pragma unroll
        for (int j = 0; j < 4; j++) {
            const int p = pb + 4 * j;
            const float4 pc = g_pc[p];
            const int g = p >> 3;
            const float mu = s_grp[g * 2 + 0];
            const float rs = s_grp[g * 2 + 1];
            const float gr = pc.z * rs;
            c1[j] = gr * pc.x;
            c2[j] = 1.f - gr * pc.y;
            c3[j] = pc.w - gr * mu;
        }
        for (int c = 0; c < C_; c += 4) {
            float xv[4], rv[4];
            #pragma unroll
            for (int i = 0; i < 4; i++) {
                xv[i] = s_x[(c + i) * H_ + h];
                rv[i] = fmaxf(xv[i], 0.f);
            }
            #pragma unroll
            for (int j = 0; j < 4; j++) {
                const float4 m4 = *(const float4*)(s_m + (pb + 4 * j) * 64 + c);
                Rm[j] += m4.x * rv[0] + m4.y * rv[1] + m4.z * rv[2] + m4.w * rv[3];
                Xm[j] += m4.x * xv[0] + m4.y * xv[1] + m4.z * xv[2] + m4.w * xv[3];
            }
        }
        float* ob = out + (size_t)b * (P_ * H_);
        #pragma unroll
        for (int j = 0; j < 4; j++)
            ob[(pb + 4 * j) * H_ + h] = c1[j] * Rm[j] + c2[j] * Xm[j] + c3[j];
    }
}

// ---------------- launch ----------------
extern "C" void kernel_launch(void* const* d_in, const int* in_sizes, int n_in,
                              void* d_out, int out_size)
{
    const float* x          = (const float*)d_in[0];
    const float* x_prompt   = (const float*)d_in[1];
    const float* emb_column = (const float*)d_in[2];
    const float* emb_prompt = (const float*)d_in[3];
    const float* lin_w      = (const float*)d_in[4];
    const float* lin_b      = (const float*)d_in[5];
    const float* ln_col_w   = (const float*)d_in[6];
    const float* ln_col_b   = (const float*)d_in[7];
    const float* ln_pr_w    = (const float*)d_in[8];
    const float* ln_pr_b    = (const float*)d_in[9];
    const float* expand_w   = (const float*)d_in[10];
    const float* gn_w       = (const float*)d_in[11];
    const float* gn_b       = (const float*)d_in[12];
    float* out = (float*)d_out;

    const int smemBytes = SM_FLOATS * (int)sizeof(float);   // 79,136 B
    cudaFuncSetAttribute(trompt_main_kernel,
                         cudaFuncAttributeMaxDynamicSharedMemorySize, smemBytes);

    setup_kernel<<<6, 256>>>(emb_column, emb_prompt, lin_w, lin_b,
                             ln_col_w, ln_col_b, ln_pr_w, ln_pr_b,
                             expand_w, gn_w, gn_b);
    trompt_main_kernel<<<B_, 512, smemBytes>>>(x, x_prompt, out);
}